// round 3
// baseline (speedup 1.0000x reference)
#include <cuda_runtime.h>
#include <math.h>

// Problem constants (fixed shapes per reference setup_inputs)
constexpr int kB   = 4;
constexpr int kTQ  = 2048;
constexpr int kTKV = 2048;
constexpr int kC   = 1024;
constexpr int kH   = 16;
constexpr int kD   = 64;
constexpr int kM   = kB * kTQ;      // 8192 rows

// Scratch (static device globals; no allocations allowed)
__device__ float g_q[(size_t)kM * kC];            // 33.5 MB  Q projection (rope'd in place)
__device__ float g_kv[(size_t)kM * 2 * kC];       // 67 MB    KV projection (K rope'd in place)
__device__ float g_attn[(size_t)kM * kC];         // 33.5 MB  attention output
__device__ float g_sin[kTKV * (kD / 2)];
__device__ float g_cos[kTKV * (kD / 2)];

// ---------------------------------------------------------------------------
// RoPE tables: angle = (t+1) * 10000^{-(2i+1)/D}, computed in double for accuracy
// ---------------------------------------------------------------------------
__global__ void rope_tables_kernel() {
    int idx = blockIdx.x * blockDim.x + threadIdx.x;
    if (idx >= kTKV * (kD / 2)) return;
    int t = idx >> 5;           // D/2 = 32
    int i = idx & 31;
    double freq = pow(10000.0, -((2.0 * i + 1.0) / (double)kD));
    double ang = (double)(t + 1) * freq;
    g_sin[idx] = (float)sin(ang);
    g_cos[idx] = (float)cos(ang);
}

// ---------------------------------------------------------------------------
// In-place RoPE on first kC columns of a [kM, ldc] matrix.
// Column c belongs to head h=c/64, pair index i=(c%64)/2.
// ---------------------------------------------------------------------------
__global__ void rope_apply_kernel(float* __restrict__ base, int ldc) {
    int idx = blockIdx.x * blockDim.x + threadIdx.x;
    const int total = kM * (kC / 2);
    if (idx >= total) return;
    int c2  = idx & (kC / 2 - 1);   // 0..511
    int row = idx >> 9;
    int t   = row & (kTQ - 1);      // T = 2048, power of two
    int i   = c2 & 31;              // pair index within head
    float s  = g_sin[t * 32 + i];
    float co = g_cos[t * 32 + i];
    float2* p = (float2*)(base + (size_t)row * ldc) + c2;
    float2 v = *p;
    *p = make_float2(v.x * co - v.y * s, v.x * s + v.y * co);
}

// ---------------------------------------------------------------------------
// fp32 GEMM: C[M,N] = A[M,K] @ W[K,N], all row-major. BM=BN=128, BK=16,
// 256 threads, 8x8 micro-tile per thread, single-stage reg prefetch.
// ---------------------------------------------------------------------------
__global__ __launch_bounds__(256)
void gemm_kernel(const float* __restrict__ A, const float* __restrict__ W,
                 float* __restrict__ Cout, int M, int N, int K) {
    constexpr int BK = 16;
    __shared__ float As[BK][132];   // transposed A tile, padded vs bank conflicts
    __shared__ float Bs[BK][128];

    const int tid = threadIdx.x;
    const int tx = tid & 15, ty = tid >> 4;
    const int m0 = blockIdx.y * 128, n0 = blockIdx.x * 128;

    float acc[8][8];
#pragma unroll
    for (int r = 0; r < 8; ++r)
#pragma unroll
        for (int c = 0; c < 8; ++c) acc[r][c] = 0.f;

    float4 a_reg[2], b_reg[2];
#pragma unroll
    for (int it = 0; it < 2; ++it) {
        int idx = tid + 256 * it;
        int r = idx >> 2, kk = (idx & 3) << 2;
        a_reg[it] = *(const float4*)(A + (size_t)(m0 + r) * K + kk);
        int br = idx >> 5, bc = (idx & 31) << 2;
        b_reg[it] = *(const float4*)(W + (size_t)br * N + n0 + bc);
    }

    const int nk = K / BK;
    for (int kt = 0; kt < nk; ++kt) {
#pragma unroll
        for (int it = 0; it < 2; ++it) {
            int idx = tid + 256 * it;
            int r = idx >> 2, kk = (idx & 3) << 2;
            As[kk + 0][r] = a_reg[it].x;
            As[kk + 1][r] = a_reg[it].y;
            As[kk + 2][r] = a_reg[it].z;
            As[kk + 3][r] = a_reg[it].w;
            int br = idx >> 5, bc = (idx & 31) << 2;
            *(float4*)(&Bs[br][bc]) = b_reg[it];
        }
        __syncthreads();

        if (kt + 1 < nk) {
            int k0 = (kt + 1) * BK;
#pragma unroll
            for (int it = 0; it < 2; ++it) {
                int idx = tid + 256 * it;
                int r = idx >> 2, kk = (idx & 3) << 2;
                a_reg[it] = *(const float4*)(A + (size_t)(m0 + r) * K + k0 + kk);
                int br = idx >> 5, bc = (idx & 31) << 2;
                b_reg[it] = *(const float4*)(W + (size_t)(k0 + br) * N + n0 + bc);
            }
        }

#pragma unroll
        for (int k = 0; k < BK; ++k) {
            float av[8], bv[8];
            *(float4*)&av[0] = *(const float4*)&As[k][ty * 4];
            *(float4*)&av[4] = *(const float4*)&As[k][64 + ty * 4];
            *(float4*)&bv[0] = *(const float4*)&Bs[k][tx * 4];
            *(float4*)&bv[4] = *(const float4*)&Bs[k][64 + tx * 4];
#pragma unroll
            for (int r = 0; r < 8; ++r)
#pragma unroll
                for (int c = 0; c < 8; ++c)
                    acc[r][c] += av[r] * bv[c];
        }
        __syncthreads();
    }

#pragma unroll
    for (int r = 0; r < 8; ++r) {
        int mm = m0 + ((r < 4) ? (ty * 4 + r) : (64 + ty * 4 + r - 4));
        float4 o;
        o.x = acc[r][0]; o.y = acc[r][1]; o.z = acc[r][2]; o.w = acc[r][3];
        *(float4*)(Cout + (size_t)mm * N + n0 + tx * 4) = o;
        o.x = acc[r][4]; o.y = acc[r][5]; o.z = acc[r][6]; o.w = acc[r][7];
        *(float4*)(Cout + (size_t)mm * N + n0 + 64 + tx * 4) = o;
    }
}

// ---------------------------------------------------------------------------
// Flash attention, fp32. One CTA = (b, h, 64 q-rows). BQ=BKV=64, D=64.
// 256 threads = 16x16; each thread owns 4x4 of S and 4x4 of O.
// Q pre-scaled by 1/sqrt(D). Online softmax with 16-lane shfl reductions.
// Masks are int32 (harness converts bool -> int32): nonzero = true.
// ---------------------------------------------------------------------------
constexpr int kFlashSmem = (4 * 64 * 64 + 128) * (int)sizeof(float);  // 66048 B

__global__ __launch_bounds__(256)
void flash_kernel(const float* __restrict__ Q, const float* __restrict__ KV,
                  const int* __restrict__ qmask,
                  const int* __restrict__ kvmask,
                  float* __restrict__ Out) {
    extern __shared__ float smf[];
    float* Qs = smf;                 // [d][i]  (d-major, 64x64)
    float* Ks = Qs + 64 * 64;        // [d][j]
    float* Vs = Ks + 64 * 64;        // [j][d]
    float* Ps = Vs + 64 * 64;        // [i][j]
    float* qm = Ps + 64 * 64;        // 64
    float* km = qm + 64;             // 64

    const int tid = threadIdx.x;
    const int tx = tid & 15, ty = tid >> 4;
    const int q0 = blockIdx.x * 64;
    const int h  = blockIdx.y;
    const int b  = blockIdx.z;
    const float scale = 0.125f;      // 1/sqrt(64)

    {
        int i  = tid & 63;
        int db = (tid >> 6) << 2;
        const float* qp = Q + (size_t)(b * kTQ + q0 + i) * kC + h * 64;
#pragma unroll
        for (int it = 0; it < 4; ++it) {
            int d = db + it * 16;
            float4 v = *(const float4*)(qp + d);
            Qs[(d + 0) * 64 + i] = v.x * scale;
            Qs[(d + 1) * 64 + i] = v.y * scale;
            Qs[(d + 2) * 64 + i] = v.z * scale;
            Qs[(d + 3) * 64 + i] = v.w * scale;
        }
        if (tid < 64) qm[tid] = (qmask[b * kTQ + q0 + tid] != 0) ? 1.f : 0.f;
    }

    float m_r[4], l_r[4], oa[4][4];
#pragma unroll
    for (int r = 0; r < 4; ++r) {
        m_r[r] = -INFINITY; l_r[r] = 0.f;
#pragma unroll
        for (int c = 0; c < 4; ++c) oa[r][c] = 0.f;
    }

    for (int kt = 0; kt < kTKV / 64; ++kt) {
        const int k0 = kt * 64;
        __syncthreads();   // previous iter's O-gemm reads of Vs/Ps done

        {
            int j  = tid & 63;
            int db = (tid >> 6) << 2;
            const float* kp = KV + (size_t)(b * kTKV + k0 + j) * (2 * kC) + h * 64;
#pragma unroll
            for (int it = 0; it < 4; ++it) {
                int d = db + it * 16;
                float4 v = *(const float4*)(kp + d);
                Ks[(d + 0) * 64 + j] = v.x;
                Ks[(d + 1) * 64 + j] = v.y;
                Ks[(d + 2) * 64 + j] = v.z;
                Ks[(d + 3) * 64 + j] = v.w;
            }
#pragma unroll
            for (int it = 0; it < 4; ++it) {
                int idx = tid + 256 * it;
                int jj = idx >> 4, dq = (idx & 15) << 2;
                const float* vp = KV + (size_t)(b * kTKV + k0 + jj) * (2 * kC) + kC + h * 64 + dq;
                *(float4*)(Vs + jj * 64 + dq) = *(const float4*)vp;
            }
            if (tid < 64) km[tid] = (kvmask[b * kTKV + k0 + tid] != 0) ? 1.f : 0.f;
        }
        __syncthreads();

        // S = (Q*scale) K^T
        float s[4][4];
#pragma unroll
        for (int r = 0; r < 4; ++r)
#pragma unroll
            for (int c = 0; c < 4; ++c) s[r][c] = 0.f;
#pragma unroll 8
        for (int d = 0; d < 64; ++d) {
            float4 a  = *(const float4*)(Qs + d * 64 + ty * 4);
            float4 bb = *(const float4*)(Ks + d * 64 + tx * 4);
            float av[4] = {a.x, a.y, a.z, a.w};
            float bv[4] = {bb.x, bb.y, bb.z, bb.w};
#pragma unroll
            for (int r = 0; r < 4; ++r)
#pragma unroll
                for (int c = 0; c < 4; ++c)
                    s[r][c] += av[r] * bv[c];
        }

        // masking: att = mask ? att : -1e9
        float qmr[4], kmc[4];
#pragma unroll
        for (int r = 0; r < 4; ++r) qmr[r] = qm[ty * 4 + r];
#pragma unroll
        for (int c = 0; c < 4; ++c) kmc[c] = km[tx * 4 + c];
#pragma unroll
        for (int r = 0; r < 4; ++r)
#pragma unroll
            for (int c = 0; c < 4; ++c)
                if (qmr[r] * kmc[c] == 0.f) s[r][c] = -1e9f;

        // online softmax (row groups = 16 lanes sharing ty within a warp)
#pragma unroll
        for (int r = 0; r < 4; ++r) {
            float mx = fmaxf(fmaxf(s[r][0], s[r][1]), fmaxf(s[r][2], s[r][3]));
#pragma unroll
            for (int off = 8; off >= 1; off >>= 1)
                mx = fmaxf(mx, __shfl_xor_sync(0xffffffffu, mx, off));
            float m_new = fmaxf(m_r[r], mx);
            float alpha = expf(m_r[r] - m_new);
            float sum = 0.f;
#pragma unroll
            for (int c = 0; c < 4; ++c) { s[r][c] = expf(s[r][c] - m_new); sum += s[r][c]; }
#pragma unroll
            for (int off = 8; off >= 1; off >>= 1)
                sum += __shfl_xor_sync(0xffffffffu, sum, off);
            l_r[r] = l_r[r] * alpha + sum;
            m_r[r] = m_new;
#pragma unroll
            for (int c = 0; c < 4; ++c) oa[r][c] *= alpha;
        }

#pragma unroll
        for (int r = 0; r < 4; ++r)
            *(float4*)(Ps + (ty * 4 + r) * 64 + tx * 4) =
                make_float4(s[r][0], s[r][1], s[r][2], s[r][3]);
        __syncthreads();

        // O += P @ V
#pragma unroll 8
        for (int j = 0; j < 64; ++j) {
            float4 v = *(const float4*)(Vs + j * 64 + tx * 4);
            float p0 = Ps[(ty * 4 + 0) * 64 + j];
            float p1 = Ps[(ty * 4 + 1) * 64 + j];
            float p2 = Ps[(ty * 4 + 2) * 64 + j];
            float p3 = Ps[(ty * 4 + 3) * 64 + j];
            oa[0][0] += p0 * v.x; oa[0][1] += p0 * v.y; oa[0][2] += p0 * v.z; oa[0][3] += p0 * v.w;
            oa[1][0] += p1 * v.x; oa[1][1] += p1 * v.y; oa[1][2] += p1 * v.z; oa[1][3] += p1 * v.w;
            oa[2][0] += p2 * v.x; oa[2][1] += p2 * v.y; oa[2][2] += p2 * v.z; oa[2][3] += p2 * v.w;
            oa[3][0] += p3 * v.x; oa[3][1] += p3 * v.y; oa[3][2] += p3 * v.z; oa[3][3] += p3 * v.w;
        }
    }

#pragma unroll
    for (int r = 0; r < 4; ++r) {
        float inv = 1.f / l_r[r];
        float4 o = make_float4(oa[r][0] * inv, oa[r][1] * inv, oa[r][2] * inv, oa[r][3] * inv);
        *(float4*)(Out + (size_t)(b * kTQ + q0 + ty * 4 + r) * kC + h * 64 + tx * 4) = o;
    }
}

// ---------------------------------------------------------------------------
extern "C" void kernel_launch(void* const* d_in, const int* in_sizes, int n_in,
                              void* d_out, int out_size) {
    const float* x_q  = (const float*)d_in[0];
    const float* x_kv = (const float*)d_in[1];
    const int* q_mask  = (const int*)d_in[2];
    const int* kv_mask = (const int*)d_in[3];
    const float* W_q  = (const float*)d_in[4];
    const float* W_kv = (const float*)d_in[5];
    const float* W_c  = (const float*)d_in[6];
    float* out = (float*)d_out;

    void* p;
    cudaGetSymbolAddress(&p, g_q);    float* gq  = (float*)p;
    cudaGetSymbolAddress(&p, g_kv);   float* gkv = (float*)p;
    cudaGetSymbolAddress(&p, g_attn); float* gat = (float*)p;

    // 1) RoPE tables (double-precision sincos, tiny)
    rope_tables_kernel<<<(kTKV * 32 + 255) / 256, 256>>>();

    // 2) Projections
    gemm_kernel<<<dim3(kC / 128, kM / 128), 256>>>(x_q, W_q, gq, kM, kC, kC);
    gemm_kernel<<<dim3(2 * kC / 128, kM / 128), 256>>>(x_kv, W_kv, gkv, kM, 2 * kC, kC);

    // 3) RoPE on Q and on the K half of KV (in place)
    int rope_threads = kM * (kC / 2);
    rope_apply_kernel<<<(rope_threads + 255) / 256, 256>>>(gq, kC);
    rope_apply_kernel<<<(rope_threads + 255) / 256, 256>>>(gkv, 2 * kC);

    // 4) Attention
    cudaFuncSetAttribute(flash_kernel, cudaFuncAttributeMaxDynamicSharedMemorySize, kFlashSmem);
    flash_kernel<<<dim3(kTQ / 64, kH, kB), 256, kFlashSmem>>>(gq, gkv, q_mask, kv_mask, gat);

    // 5) Output projection -> d_out
    gemm_kernel<<<dim3(kC / 128, kM / 128), 256>>>(gat, W_c, out, kM, kC, kC);
}

// round 4
// speedup vs baseline: 1.3945x; 1.3945x over previous
#include <cuda_runtime.h>
#include <cuda_bf16.h>
#include <math.h>
#include <stdint.h>

// Problem constants (fixed shapes per reference setup_inputs)
constexpr int kB   = 4;
constexpr int kTQ  = 2048;
constexpr int kTKV = 2048;
constexpr int kC   = 1024;
constexpr int kD   = 64;
constexpr int kH   = 16;
constexpr int kM   = kB * kTQ;      // 8192 rows

// Scratch (static device globals; no allocations allowed)
__device__ float g_q[(size_t)kM * kC];
__device__ float g_kv[(size_t)kM * 2 * kC];
__device__ float g_attn[(size_t)kM * kC];
__device__ float g_sin[kTKV * (kD / 2)];
__device__ float g_cos[kTKV * (kD / 2)];

// ---------------------------------------------------------------------------
// RoPE tables
// ---------------------------------------------------------------------------
__global__ void rope_tables_kernel() {
    int idx = blockIdx.x * blockDim.x + threadIdx.x;
    if (idx >= kTKV * (kD / 2)) return;
    int t = idx >> 5;
    int i = idx & 31;
    double freq = pow(10000.0, -((2.0 * i + 1.0) / (double)kD));
    double ang = (double)(t + 1) * freq;
    g_sin[idx] = (float)sin(ang);
    g_cos[idx] = (float)cos(ang);
}

__global__ void rope_apply_kernel(float* __restrict__ base, int ldc) {
    int idx = blockIdx.x * blockDim.x + threadIdx.x;
    const int total = kM * (kC / 2);
    if (idx >= total) return;
    int c2  = idx & (kC / 2 - 1);
    int row = idx >> 9;
    int t   = row & (kTQ - 1);
    int i   = c2 & 31;
    float s  = g_sin[t * 32 + i];
    float co = g_cos[t * 32 + i];
    float2* p = (float2*)(base + (size_t)row * ldc) + c2;
    float2 v = *p;
    *p = make_float2(v.x * co - v.y * s, v.x * s + v.y * co);
}

// ---------------------------------------------------------------------------
// bf16x3 tensor-core GEMM: C[M,N] = A[M,K] @ W[K,N] (row-major, fp32 in/out).
// Each fp32 is split x = hi + lo (bf16 each); product uses hi*hi + hi*lo + lo*hi.
// CTA: 128x128x32 tile, 256 threads = 8 warps in 2(m) x 4(n); warp tile 64x32.
// mma.sync.m16n8k16 fragments fed by ldmatrix from padded smem.
// ---------------------------------------------------------------------------
__device__ __forceinline__ uint32_t smem_u32(const void* p) {
    return (uint32_t)__cvta_generic_to_shared(p);
}
__device__ __forceinline__ void ldsm_x4(uint32_t* r, uint32_t addr) {
    asm volatile("ldmatrix.sync.aligned.m8n8.x4.shared.b16 {%0,%1,%2,%3}, [%4];"
                 : "=r"(r[0]), "=r"(r[1]), "=r"(r[2]), "=r"(r[3]) : "r"(addr));
}
__device__ __forceinline__ void ldsm_x2(uint32_t* r, uint32_t addr) {
    asm volatile("ldmatrix.sync.aligned.m8n8.x2.shared.b16 {%0,%1}, [%2];"
                 : "=r"(r[0]), "=r"(r[1]) : "r"(addr));
}
__device__ __forceinline__ void mma16816(float* c, const uint32_t* a, const uint32_t* b) {
    asm volatile(
        "mma.sync.aligned.m16n8k16.row.col.f32.bf16.bf16.f32 "
        "{%0,%1,%2,%3}, {%4,%5,%6,%7}, {%8,%9}, {%0,%1,%2,%3};\n"
        : "+f"(c[0]), "+f"(c[1]), "+f"(c[2]), "+f"(c[3])
        : "r"(a[0]), "r"(a[1]), "r"(a[2]), "r"(a[3]), "r"(b[0]), "r"(b[1]));
}
__device__ __forceinline__ void split_bf16(float x, __nv_bfloat16& h, __nv_bfloat16& l) {
    h = __float2bfloat16(x);
    l = __float2bfloat16(x - __bfloat162float(h));
}
__device__ __forceinline__ uint32_t pack2(__nv_bfloat16 a, __nv_bfloat16 b) {
    __nv_bfloat162 t; t.x = a; t.y = b;
    return *reinterpret_cast<uint32_t*>(&t);
}

constexpr int kLD = 40;   // bf16 elements per smem row (80 bytes, conflict-free)

__global__ __launch_bounds__(256)
void gemm_bf16x3_kernel(const float* __restrict__ A, const float* __restrict__ W,
                        float* __restrict__ C, int M, int N, int K) {
    __shared__ __align__(16) __nv_bfloat16 sAhi[128 * kLD];
    __shared__ __align__(16) __nv_bfloat16 sAlo[128 * kLD];
    __shared__ __align__(16) __nv_bfloat16 sBhi[128 * kLD];   // [n][k]
    __shared__ __align__(16) __nv_bfloat16 sBlo[128 * kLD];

    const int tid  = threadIdx.x;
    const int warp = tid >> 5, lane = tid & 31;
    const int wm = warp >> 2, wn = warp & 3;          // 2 x 4 warp grid
    const int m0 = blockIdx.y * 128, n0 = blockIdx.x * 128;

    // gmem load mapping
    const int a_c = tid & 7;          // float4 column within 32-wide k (k = a_c*4)
    const int a_r = tid >> 3;         // row 0..31, +32 strides
    const int b_kb = tid >> 5;        // k sub-block 0..7 (4 k-rows each)
    const int b_nb = tid & 31;        // n sub-block (4 cols each)

    float4 aReg[4], bReg[4];
#pragma unroll
    for (int i = 0; i < 4; ++i)
        aReg[i] = *(const float4*)(A + (size_t)(m0 + a_r + i * 32) * K + a_c * 4);
#pragma unroll
    for (int i = 0; i < 4; ++i)
        bReg[i] = *(const float4*)(W + (size_t)(b_kb * 4 + i) * N + n0 + b_nb * 4);

    float acc[4][4][4];
#pragma unroll
    for (int mt = 0; mt < 4; ++mt)
#pragma unroll
        for (int nt = 0; nt < 4; ++nt)
#pragma unroll
            for (int e = 0; e < 4; ++e) acc[mt][nt][e] = 0.f;

    const uint32_t sAhi_b = smem_u32(sAhi), sAlo_b = smem_u32(sAlo);
    const uint32_t sBhi_b = smem_u32(sBhi), sBlo_b = smem_u32(sBlo);
    const int g8 = lane & 7, tq = lane >> 3;

    const int nk = K / 32;
    for (int kt = 0; kt < nk; ++kt) {
        // ---- convert + store current tile to smem ----
#pragma unroll
        for (int i = 0; i < 4; ++i) {
            float4 v = aReg[i];
            __nv_bfloat16 h0, h1, h2, h3, l0, l1, l2, l3;
            split_bf16(v.x, h0, l0); split_bf16(v.y, h1, l1);
            split_bf16(v.z, h2, l2); split_bf16(v.w, h3, l3);
            int row = a_r + i * 32;
            *(uint2*)&sAhi[row * kLD + a_c * 4] = make_uint2(pack2(h0, h1), pack2(h2, h3));
            *(uint2*)&sAlo[row * kLD + a_c * 4] = make_uint2(pack2(l0, l1), pack2(l2, l3));
        }
        {
            float bx[4][4];
#pragma unroll
            for (int i = 0; i < 4; ++i) {
                bx[i][0] = bReg[i].x; bx[i][1] = bReg[i].y;
                bx[i][2] = bReg[i].z; bx[i][3] = bReg[i].w;
            }
#pragma unroll
            for (int j = 0; j < 4; ++j) {
                __nv_bfloat16 h[4], l[4];
#pragma unroll
                for (int i = 0; i < 4; ++i) split_bf16(bx[i][j], h[i], l[i]);
                int nrow = b_nb * 4 + j;
                *(uint2*)&sBhi[nrow * kLD + b_kb * 4] = make_uint2(pack2(h[0], h[1]), pack2(h[2], h[3]));
                *(uint2*)&sBlo[nrow * kLD + b_kb * 4] = make_uint2(pack2(l[0], l[1]), pack2(l[2], l[3]));
            }
        }
        __syncthreads();

        // ---- prefetch next tile from gmem ----
        if (kt + 1 < nk) {
            int k0 = (kt + 1) * 32;
#pragma unroll
            for (int i = 0; i < 4; ++i)
                aReg[i] = *(const float4*)(A + (size_t)(m0 + a_r + i * 32) * K + k0 + a_c * 4);
#pragma unroll
            for (int i = 0; i < 4; ++i)
                bReg[i] = *(const float4*)(W + (size_t)(k0 + b_kb * 4 + i) * N + n0 + b_nb * 4);
        }

        // ---- mma over 2 k16 sub-steps ----
#pragma unroll
        for (int s = 0; s < 2; ++s) {
            uint32_t bh[4][2], bl[4][2];
#pragma unroll
            for (int nt = 0; nt < 4; ++nt) {
                uint32_t off = (uint32_t)(((wn * 32 + nt * 8 + g8) * kLD + s * 16 + ((tq & 1) << 3)) * 2);
                ldsm_x2(bh[nt], sBhi_b + off);
                ldsm_x2(bl[nt], sBlo_b + off);
            }
#pragma unroll
            for (int mt = 0; mt < 4; ++mt) {
                uint32_t offA = (uint32_t)(((wm * 64 + mt * 16 + ((tq & 1) << 3) + g8) * kLD
                                            + s * 16 + ((tq >> 1) << 3)) * 2);
                uint32_t ah[4], al[4];
                ldsm_x4(ah, sAhi_b + offA);
                ldsm_x4(al, sAlo_b + offA);
#pragma unroll
                for (int nt = 0; nt < 4; ++nt) {
                    mma16816(acc[mt][nt], ah, bh[nt]);
                    mma16816(acc[mt][nt], ah, bl[nt]);
                    mma16816(acc[mt][nt], al, bh[nt]);
                }
            }
        }
        __syncthreads();
    }

    // ---- epilogue ----
    const int gq = lane >> 2, tg = lane & 3;
#pragma unroll
    for (int mt = 0; mt < 4; ++mt) {
#pragma unroll
        for (int nt = 0; nt < 4; ++nt) {
            int row = m0 + wm * 64 + mt * 16 + gq;
            int col = n0 + wn * 32 + nt * 8 + 2 * tg;
            *(float2*)(C + (size_t)row * N + col)       = make_float2(acc[mt][nt][0], acc[mt][nt][1]);
            *(float2*)(C + (size_t)(row + 8) * N + col) = make_float2(acc[mt][nt][2], acc[mt][nt][3]);
        }
    }
}

// ---------------------------------------------------------------------------
// Flash attention, fp32 (unchanged from R3 passing version).
// ---------------------------------------------------------------------------
constexpr int kFlashSmem = (4 * 64 * 64 + 128) * (int)sizeof(float);

__global__ __launch_bounds__(256)
void flash_kernel(const float* __restrict__ Q, const float* __restrict__ KV,
                  const int* __restrict__ qmask,
                  const int* __restrict__ kvmask,
                  float* __restrict__ Out) {
    extern __shared__ float smf[];
    float* Qs = smf;
    float* Ks = Qs + 64 * 64;
    float* Vs = Ks + 64 * 64;
    float* Ps = Vs + 64 * 64;
    float* qm = Ps + 64 * 64;
    float* km = qm + 64;

    const int tid = threadIdx.x;
    const int tx = tid & 15, ty = tid >> 4;
    const int q0 = blockIdx.x * 64;
    const int h  = blockIdx.y;
    const int b  = blockIdx.z;
    const float scale = 0.125f;

    {
        int i  = tid & 63;
        int db = (tid >> 6) << 2;
        const float* qp = Q + (size_t)(b * kTQ + q0 + i) * kC + h * 64;
#pragma unroll
        for (int it = 0; it < 4; ++it) {
            int d = db + it * 16;
            float4 v = *(const float4*)(qp + d);
            Qs[(d + 0) * 64 + i] = v.x * scale;
            Qs[(d + 1) * 64 + i] = v.y * scale;
            Qs[(d + 2) * 64 + i] = v.z * scale;
            Qs[(d + 3) * 64 + i] = v.w * scale;
        }
        if (tid < 64) qm[tid] = (qmask[b * kTQ + q0 + tid] != 0) ? 1.f : 0.f;
    }

    float m_r[4], l_r[4], oa[4][4];
#pragma unroll
    for (int r = 0; r < 4; ++r) {
        m_r[r] = -INFINITY; l_r[r] = 0.f;
#pragma unroll
        for (int c = 0; c < 4; ++c) oa[r][c] = 0.f;
    }

    for (int kt = 0; kt < kTKV / 64; ++kt) {
        const int k0 = kt * 64;
        __syncthreads();

        {
            int j  = tid & 63;
            int db = (tid >> 6) << 2;
            const float* kp = KV + (size_t)(b * kTKV + k0 + j) * (2 * kC) + h * 64;
#pragma unroll
            for (int it = 0; it < 4; ++it) {
                int d = db + it * 16;
                float4 v = *(const float4*)(kp + d);
                Ks[(d + 0) * 64 + j] = v.x;
                Ks[(d + 1) * 64 + j] = v.y;
                Ks[(d + 2) * 64 + j] = v.z;
                Ks[(d + 3) * 64 + j] = v.w;
            }
#pragma unroll
            for (int it = 0; it < 4; ++it) {
                int idx = tid + 256 * it;
                int jj = idx >> 4, dq = (idx & 15) << 2;
                const float* vp = KV + (size_t)(b * kTKV + k0 + jj) * (2 * kC) + kC + h * 64 + dq;
                *(float4*)(Vs + jj * 64 + dq) = *(const float4*)vp;
            }
            if (tid < 64) km[tid] = (kvmask[b * kTKV + k0 + tid] != 0) ? 1.f : 0.f;
        }
        __syncthreads();

        float s[4][4];
#pragma unroll
        for (int r = 0; r < 4; ++r)
#pragma unroll
            for (int c = 0; c < 4; ++c) s[r][c] = 0.f;
#pragma unroll 8
        for (int d = 0; d < 64; ++d) {
            float4 a  = *(const float4*)(Qs + d * 64 + ty * 4);
            float4 bb = *(const float4*)(Ks + d * 64 + tx * 4);
            float av[4] = {a.x, a.y, a.z, a.w};
            float bv[4] = {bb.x, bb.y, bb.z, bb.w};
#pragma unroll
            for (int r = 0; r < 4; ++r)
#pragma unroll
                for (int c = 0; c < 4; ++c)
                    s[r][c] += av[r] * bv[c];
        }

        float qmr[4], kmc[4];
#pragma unroll
        for (int r = 0; r < 4; ++r) qmr[r] = qm[ty * 4 + r];
#pragma unroll
        for (int c = 0; c < 4; ++c) kmc[c] = km[tx * 4 + c];
#pragma unroll
        for (int r = 0; r < 4; ++r)
#pragma unroll
            for (int c = 0; c < 4; ++c)
                if (qmr[r] * kmc[c] == 0.f) s[r][c] = -1e9f;

#pragma unroll
        for (int r = 0; r < 4; ++r) {
            float mx = fmaxf(fmaxf(s[r][0], s[r][1]), fmaxf(s[r][2], s[r][3]));
#pragma unroll
            for (int off = 8; off >= 1; off >>= 1)
                mx = fmaxf(mx, __shfl_xor_sync(0xffffffffu, mx, off));
            float m_new = fmaxf(m_r[r], mx);
            float alpha = expf(m_r[r] - m_new);
            float sum = 0.f;
#pragma unroll
            for (int c = 0; c < 4; ++c) { s[r][c] = expf(s[r][c] - m_new); sum += s[r][c]; }
#pragma unroll
            for (int off = 8; off >= 1; off >>= 1)
                sum += __shfl_xor_sync(0xffffffffu, sum, off);
            l_r[r] = l_r[r] * alpha + sum;
            m_r[r] = m_new;
#pragma unroll
            for (int c = 0; c < 4; ++c) oa[r][c] *= alpha;
        }

#pragma unroll
        for (int r = 0; r < 4; ++r)
            *(float4*)(Ps + (ty * 4 + r) * 64 + tx * 4) =
                make_float4(s[r][0], s[r][1], s[r][2], s[r][3]);
        __syncthreads();

#pragma unroll 8
        for (int j = 0; j < 64; ++j) {
            float4 v = *(const float4*)(Vs + j * 64 + tx * 4);
            float p0 = Ps[(ty * 4 + 0) * 64 + j];
            float p1 = Ps[(ty * 4 + 1) * 64 + j];
            float p2 = Ps[(ty * 4 + 2) * 64 + j];
            float p3 = Ps[(ty * 4 + 3) * 64 + j];
            oa[0][0] += p0 * v.x; oa[0][1] += p0 * v.y; oa[0][2] += p0 * v.z; oa[0][3] += p0 * v.w;
            oa[1][0] += p1 * v.x; oa[1][1] += p1 * v.y; oa[1][2] += p1 * v.z; oa[1][3] += p1 * v.w;
            oa[2][0] += p2 * v.x; oa[2][1] += p2 * v.y; oa[2][2] += p2 * v.z; oa[2][3] += p2 * v.w;
            oa[3][0] += p3 * v.x; oa[3][1] += p3 * v.y; oa[3][2] += p3 * v.z; oa[3][3] += p3 * v.w;
        }
    }

#pragma unroll
    for (int r = 0; r < 4; ++r) {
        float inv = 1.f / l_r[r];
        float4 o = make_float4(oa[r][0] * inv, oa[r][1] * inv, oa[r][2] * inv, oa[r][3] * inv);
        *(float4*)(Out + (size_t)(b * kTQ + q0 + ty * 4 + r) * kC + h * 64 + tx * 4) = o;
    }
}

// ---------------------------------------------------------------------------
extern "C" void kernel_launch(void* const* d_in, const int* in_sizes, int n_in,
                              void* d_out, int out_size) {
    const float* x_q  = (const float*)d_in[0];
    const float* x_kv = (const float*)d_in[1];
    const int* q_mask  = (const int*)d_in[2];
    const int* kv_mask = (const int*)d_in[3];
    const float* W_q  = (const float*)d_in[4];
    const float* W_kv = (const float*)d_in[5];
    const float* W_c  = (const float*)d_in[6];
    float* out = (float*)d_out;

    void* p;
    cudaGetSymbolAddress(&p, g_q);    float* gq  = (float*)p;
    cudaGetSymbolAddress(&p, g_kv);   float* gkv = (float*)p;
    cudaGetSymbolAddress(&p, g_attn); float* gat = (float*)p;

    rope_tables_kernel<<<(kTKV * 32 + 255) / 256, 256>>>();

    gemm_bf16x3_kernel<<<dim3(kC / 128, kM / 128), 256>>>(x_q, W_q, gq, kM, kC, kC);
    gemm_bf16x3_kernel<<<dim3(2 * kC / 128, kM / 128), 256>>>(x_kv, W_kv, gkv, kM, 2 * kC, kC);

    int rope_threads = kM * (kC / 2);
    rope_apply_kernel<<<(rope_threads + 255) / 256, 256>>>(gq, kC);
    rope_apply_kernel<<<(rope_threads + 255) / 256, 256>>>(gkv, 2 * kC);

    cudaFuncSetAttribute(flash_kernel, cudaFuncAttributeMaxDynamicSharedMemorySize, kFlashSmem);
    flash_kernel<<<dim3(kTQ / 64, kH, kB), 256, kFlashSmem>>>(gq, gkv, q_mask, kv_mask, gat);

    gemm_bf16x3_kernel<<<dim3(kC / 128, kM / 128), 256>>>(gat, W_c, out, kM, kC, kC);
}

// round 5
// speedup vs baseline: 2.5931x; 1.8595x over previous
#include <cuda_runtime.h>
#include <cuda_bf16.h>
#include <math.h>
#include <stdint.h>

constexpr int kB   = 4;
constexpr int kTQ  = 2048;
constexpr int kTKV = 2048;
constexpr int kC   = 1024;
constexpr int kD   = 64;
constexpr int kH   = 16;
constexpr int kM   = kB * kTQ;

__device__ float g_q[(size_t)kM * kC];
__device__ float g_kv[(size_t)kM * 2 * kC];
__device__ float g_attn[(size_t)kM * kC];
__device__ float g_sin[kTKV * (kD / 2)];
__device__ float g_cos[kTKV * (kD / 2)];

// ---------------------------------------------------------------------------
__global__ void rope_tables_kernel() {
    int idx = blockIdx.x * blockDim.x + threadIdx.x;
    if (idx >= kTKV * (kD / 2)) return;
    int t = idx >> 5;
    int i = idx & 31;
    double freq = pow(10000.0, -((2.0 * i + 1.0) / (double)kD));
    double ang = (double)(t + 1) * freq;
    g_sin[idx] = (float)sin(ang);
    g_cos[idx] = (float)cos(ang);
}

__global__ void rope_apply_kernel(float* __restrict__ base, int ldc) {
    int idx = blockIdx.x * blockDim.x + threadIdx.x;
    const int total = kM * (kC / 2);
    if (idx >= total) return;
    int c2  = idx & (kC / 2 - 1);
    int row = idx >> 9;
    int t   = row & (kTQ - 1);
    int i   = c2 & 31;
    float s  = g_sin[t * 32 + i];
    float co = g_cos[t * 32 + i];
    float2* p = (float2*)(base + (size_t)row * ldc) + c2;
    float2 v = *p;
    *p = make_float2(v.x * co - v.y * s, v.x * s + v.y * co);
}

// ---------------------------------------------------------------------------
// Common mma helpers
// ---------------------------------------------------------------------------
__device__ __forceinline__ uint32_t smem_u32(const void* p) {
    return (uint32_t)__cvta_generic_to_shared(p);
}
__device__ __forceinline__ void ldsm_x4(uint32_t* r, uint32_t addr) {
    asm volatile("ldmatrix.sync.aligned.m8n8.x4.shared.b16 {%0,%1,%2,%3}, [%4];"
                 : "=r"(r[0]), "=r"(r[1]), "=r"(r[2]), "=r"(r[3]) : "r"(addr));
}
__device__ __forceinline__ void ldsm_x2(uint32_t* r, uint32_t addr) {
    asm volatile("ldmatrix.sync.aligned.m8n8.x2.shared.b16 {%0,%1}, [%2];"
                 : "=r"(r[0]), "=r"(r[1]) : "r"(addr));
}
__device__ __forceinline__ void ldsm_x2_trans(uint32_t* r, uint32_t addr) {
    asm volatile("ldmatrix.sync.aligned.m8n8.x2.trans.shared.b16 {%0,%1}, [%2];"
                 : "=r"(r[0]), "=r"(r[1]) : "r"(addr));
}
__device__ __forceinline__ void mma16816(float* c, const uint32_t* a, const uint32_t* b) {
    asm volatile(
        "mma.sync.aligned.m16n8k16.row.col.f32.bf16.bf16.f32 "
        "{%0,%1,%2,%3}, {%4,%5,%6,%7}, {%8,%9}, {%0,%1,%2,%3};\n"
        : "+f"(c[0]), "+f"(c[1]), "+f"(c[2]), "+f"(c[3])
        : "r"(a[0]), "r"(a[1]), "r"(a[2]), "r"(a[3]), "r"(b[0]), "r"(b[1]));
}
__device__ __forceinline__ void split_bf16(float x, __nv_bfloat16& h, __nv_bfloat16& l) {
    h = __float2bfloat16(x);
    l = __float2bfloat16(x - __bfloat162float(h));
}
__device__ __forceinline__ uint32_t pack2(__nv_bfloat16 a, __nv_bfloat16 b) {
    __nv_bfloat162 t; t.x = a; t.y = b;
    return *reinterpret_cast<uint32_t*>(&t);
}
// pack {lo, hi} into bf16x2 with rn
__device__ __forceinline__ uint32_t cvt2_bf16(float lo, float hi) {
    uint32_t r;
    asm("cvt.rn.bf16x2.f32 %0, %1, %2;" : "=r"(r) : "f"(hi), "f"(lo));
    return r;
}

// ---------------------------------------------------------------------------
// bf16x3 tensor-core GEMM (unchanged from R4, proven)
// ---------------------------------------------------------------------------
constexpr int kLD = 40;

__global__ __launch_bounds__(256)
void gemm_bf16x3_kernel(const float* __restrict__ A, const float* __restrict__ W,
                        float* __restrict__ C, int M, int N, int K) {
    __shared__ __align__(16) __nv_bfloat16 sAhi[128 * kLD];
    __shared__ __align__(16) __nv_bfloat16 sAlo[128 * kLD];
    __shared__ __align__(16) __nv_bfloat16 sBhi[128 * kLD];
    __shared__ __align__(16) __nv_bfloat16 sBlo[128 * kLD];

    const int tid  = threadIdx.x;
    const int warp = tid >> 5, lane = tid & 31;
    const int wm = warp >> 2, wn = warp & 3;
    const int m0 = blockIdx.y * 128, n0 = blockIdx.x * 128;

    const int a_c = tid & 7;
    const int a_r = tid >> 3;
    const int b_kb = tid >> 5;
    const int b_nb = tid & 31;

    float4 aReg[4], bReg[4];
#pragma unroll
    for (int i = 0; i < 4; ++i)
        aReg[i] = *(const float4*)(A + (size_t)(m0 + a_r + i * 32) * K + a_c * 4);
#pragma unroll
    for (int i = 0; i < 4; ++i)
        bReg[i] = *(const float4*)(W + (size_t)(b_kb * 4 + i) * N + n0 + b_nb * 4);

    float acc[4][4][4];
#pragma unroll
    for (int mt = 0; mt < 4; ++mt)
#pragma unroll
        for (int nt = 0; nt < 4; ++nt)
#pragma unroll
            for (int e = 0; e < 4; ++e) acc[mt][nt][e] = 0.f;

    const uint32_t sAhi_b = smem_u32(sAhi), sAlo_b = smem_u32(sAlo);
    const uint32_t sBhi_b = smem_u32(sBhi), sBlo_b = smem_u32(sBlo);
    const int g8 = lane & 7, tq = lane >> 3;

    const int nk = K / 32;
    for (int kt = 0; kt < nk; ++kt) {
#pragma unroll
        for (int i = 0; i < 4; ++i) {
            float4 v = aReg[i];
            __nv_bfloat16 h0, h1, h2, h3, l0, l1, l2, l3;
            split_bf16(v.x, h0, l0); split_bf16(v.y, h1, l1);
            split_bf16(v.z, h2, l2); split_bf16(v.w, h3, l3);
            int row = a_r + i * 32;
            *(uint2*)&sAhi[row * kLD + a_c * 4] = make_uint2(pack2(h0, h1), pack2(h2, h3));
            *(uint2*)&sAlo[row * kLD + a_c * 4] = make_uint2(pack2(l0, l1), pack2(l2, l3));
        }
        {
            float bx[4][4];
#pragma unroll
            for (int i = 0; i < 4; ++i) {
                bx[i][0] = bReg[i].x; bx[i][1] = bReg[i].y;
                bx[i][2] = bReg[i].z; bx[i][3] = bReg[i].w;
            }
#pragma unroll
            for (int j = 0; j < 4; ++j) {
                __nv_bfloat16 h[4], l[4];
#pragma unroll
                for (int i = 0; i < 4; ++i) split_bf16(bx[i][j], h[i], l[i]);
                int nrow = b_nb * 4 + j;
                *(uint2*)&sBhi[nrow * kLD + b_kb * 4] = make_uint2(pack2(h[0], h[1]), pack2(h[2], h[3]));
                *(uint2*)&sBlo[nrow * kLD + b_kb * 4] = make_uint2(pack2(l[0], l[1]), pack2(l[2], l[3]));
            }
        }
        __syncthreads();

        if (kt + 1 < nk) {
            int k0 = (kt + 1) * 32;
#pragma unroll
            for (int i = 0; i < 4; ++i)
                aReg[i] = *(const float4*)(A + (size_t)(m0 + a_r + i * 32) * K + k0 + a_c * 4);
#pragma unroll
            for (int i = 0; i < 4; ++i)
                bReg[i] = *(const float4*)(W + (size_t)(k0 + b_kb * 4 + i) * N + n0 + b_nb * 4);
        }

#pragma unroll
        for (int s = 0; s < 2; ++s) {
            uint32_t bh[4][2], bl[4][2];
#pragma unroll
            for (int nt = 0; nt < 4; ++nt) {
                uint32_t off = (uint32_t)(((wn * 32 + nt * 8 + g8) * kLD + s * 16 + ((tq & 1) << 3)) * 2);
                ldsm_x2(bh[nt], sBhi_b + off);
                ldsm_x2(bl[nt], sBlo_b + off);
            }
#pragma unroll
            for (int mt = 0; mt < 4; ++mt) {
                uint32_t offA = (uint32_t)(((wm * 64 + mt * 16 + ((tq & 1) << 3) + g8) * kLD
                                            + s * 16 + ((tq >> 1) << 3)) * 2);
                uint32_t ah[4], al[4];
                ldsm_x4(ah, sAhi_b + offA);
                ldsm_x4(al, sAlo_b + offA);
#pragma unroll
                for (int nt = 0; nt < 4; ++nt) {
                    mma16816(acc[mt][nt], ah, bh[nt]);
                    mma16816(acc[mt][nt], ah, bl[nt]);
                    mma16816(acc[mt][nt], al, bh[nt]);
                }
            }
        }
        __syncthreads();
    }

    const int gq = lane >> 2, tg = lane & 3;
#pragma unroll
    for (int mt = 0; mt < 4; ++mt) {
#pragma unroll
        for (int nt = 0; nt < 4; ++nt) {
            int row = m0 + wm * 64 + mt * 16 + gq;
            int col = n0 + wn * 32 + nt * 8 + 2 * tg;
            *(float2*)(C + (size_t)row * N + col)       = make_float2(acc[mt][nt][0], acc[mt][nt][1]);
            *(float2*)(C + (size_t)(row + 8) * N + col) = make_float2(acc[mt][nt][2], acc[mt][nt][3]);
        }
    }
}

// ---------------------------------------------------------------------------
// Tensor-core flash attention (bf16x3). CTA = (128 q-rows, head h, batch b).
// 8 warps x 16 q-rows. KV tiles of 64, double-buffered smem.
// S = Qhi*Khi + Qhi*Klo + Qlo*Khi ; O += Phi*Vhi + Plo*Vhi + Phi*Vlo.
// ---------------------------------------------------------------------------
constexpr int kFQ = 128 * 72;   // Q smem elems (hi or lo)
constexpr int kFT = 64 * 72;    // K/V tile smem elems per buffer
constexpr int kFlashSmem = (2 * kFQ + 8 * kFT) * 2 + 2 * 64 * 4;  // 111104 B

__global__ __launch_bounds__(256, 2)
void flash_mma_kernel(const float* __restrict__ Q, const float* __restrict__ KV,
                      const int* __restrict__ qmask, const int* __restrict__ kvmask,
                      float* __restrict__ Out) {
    extern __shared__ char smc[];
    __nv_bfloat16* Qhi = (__nv_bfloat16*)smc;
    __nv_bfloat16* Qlo = Qhi + kFQ;
    __nv_bfloat16* Khi = Qlo + kFQ;          // [2][64*72]
    __nv_bfloat16* Klo = Khi + 2 * kFT;
    __nv_bfloat16* Vhi = Klo + 2 * kFT;
    __nv_bfloat16* Vlo = Vhi + 2 * kFT;
    float* km = (float*)(Vlo + 2 * kFT);     // [2][64]

    const int tid = threadIdx.x;
    const int warp = tid >> 5, lane = tid & 31;
    const int g = lane >> 2, tg = lane & 3;
    const int m0w = warp * 16;
    const int q0 = blockIdx.x * 128;
    const int h  = blockIdx.y;
    const int b  = blockIdx.z;

    // ---- load Q (scaled by 1/8), split to Qhi/Qlo ----
    {
        int row = tid >> 1, cb = (tid & 1) * 32;
        const float* qp = Q + (size_t)(b * kTQ + q0 + row) * kC + h * 64 + cb;
#pragma unroll
        for (int j = 0; j < 8; ++j) {
            float4 v = *(const float4*)(qp + j * 4);
            v.x *= 0.125f; v.y *= 0.125f; v.z *= 0.125f; v.w *= 0.125f;
            __nv_bfloat16 h0, h1, h2, h3, l0, l1, l2, l3;
            split_bf16(v.x, h0, l0); split_bf16(v.y, h1, l1);
            split_bf16(v.z, h2, l2); split_bf16(v.w, h3, l3);
            int idx = row * 72 + cb + j * 4;
            *(uint2*)&Qhi[idx] = make_uint2(pack2(h0, h1), pack2(h2, h3));
            *(uint2*)&Qlo[idx] = make_uint2(pack2(l0, l1), pack2(l2, l3));
        }
    }

    // ---- prologue: tile 0 -> buffer 0 ----
    {
        int j = tid >> 2, cb = (tid & 3) * 16;
        const float* kp = KV + (size_t)(b * kTKV + j) * (2 * kC) + h * 64 + cb;
        const float* vp = kp + kC;
#pragma unroll
        for (int jj = 0; jj < 4; ++jj) {
            float4 v = *(const float4*)(kp + jj * 4);
            __nv_bfloat16 h0, h1, h2, h3, l0, l1, l2, l3;
            split_bf16(v.x, h0, l0); split_bf16(v.y, h1, l1);
            split_bf16(v.z, h2, l2); split_bf16(v.w, h3, l3);
            int idx = j * 72 + cb + jj * 4;
            *(uint2*)&Khi[idx] = make_uint2(pack2(h0, h1), pack2(h2, h3));
            *(uint2*)&Klo[idx] = make_uint2(pack2(l0, l1), pack2(l2, l3));
            v = *(const float4*)(vp + jj * 4);
            split_bf16(v.x, h0, l0); split_bf16(v.y, h1, l1);
            split_bf16(v.z, h2, l2); split_bf16(v.w, h3, l3);
            *(uint2*)&Vhi[idx] = make_uint2(pack2(h0, h1), pack2(h2, h3));
            *(uint2*)&Vlo[idx] = make_uint2(pack2(l0, l1), pack2(l2, l3));
        }
        if (tid < 64) km[tid] = (kvmask[b * kTKV + tid] != 0) ? 1.f : 0.f;
    }

    const float qok_g  = (qmask[b * kTQ + q0 + m0w + g]     != 0) ? 1.f : 0.f;
    const float qok_g8 = (qmask[b * kTQ + q0 + m0w + g + 8] != 0) ? 1.f : 0.f;

    float o[8][4];
#pragma unroll
    for (int nt = 0; nt < 8; ++nt)
#pragma unroll
        for (int e = 0; e < 4; ++e) o[nt][e] = 0.f;
    float m_g = -INFINITY, m_g8 = -INFINITY, l_g = 0.f, l_g8 = 0.f;

    const uint32_t Qhi_b = smem_u32(Qhi), Qlo_b = smem_u32(Qlo);
    const uint32_t Khi_b = smem_u32(Khi), Klo_b = smem_u32(Klo);
    const uint32_t Vhi_b = smem_u32(Vhi), Vlo_b = smem_u32(Vlo);

    const int nTiles = kTKV / 64;
    for (int kt = 0; kt < nTiles; ++kt) {
        __syncthreads();
        const int buf = kt & 1;
        const uint32_t kOff = (uint32_t)buf * (kFT * 2);

        // ---- load+split next tile into other buffer ----
        if (kt + 1 < nTiles) {
            int k0n = (kt + 1) * 64;
            int nb = buf ^ 1;
            int j = tid >> 2, cb = (tid & 3) * 16;
            const float* kp = KV + (size_t)(b * kTKV + k0n + j) * (2 * kC) + h * 64 + cb;
            const float* vp = kp + kC;
#pragma unroll
            for (int jj = 0; jj < 4; ++jj) {
                float4 v = *(const float4*)(kp + jj * 4);
                __nv_bfloat16 h0, h1, h2, h3, l0, l1, l2, l3;
                split_bf16(v.x, h0, l0); split_bf16(v.y, h1, l1);
                split_bf16(v.z, h2, l2); split_bf16(v.w, h3, l3);
                int idx = nb * kFT + j * 72 + cb + jj * 4;
                *(uint2*)&Khi[idx] = make_uint2(pack2(h0, h1), pack2(h2, h3));
                *(uint2*)&Klo[idx] = make_uint2(pack2(l0, l1), pack2(l2, l3));
                v = *(const float4*)(vp + jj * 4);
                split_bf16(v.x, h0, l0); split_bf16(v.y, h1, l1);
                split_bf16(v.z, h2, l2); split_bf16(v.w, h3, l3);
                *(uint2*)&Vhi[idx] = make_uint2(pack2(h0, h1), pack2(h2, h3));
                *(uint2*)&Vlo[idx] = make_uint2(pack2(l0, l1), pack2(l2, l3));
            }
            if (tid < 64) km[nb * 64 + tid] = (kvmask[b * kTKV + k0n + tid] != 0) ? 1.f : 0.f;
        }

        // ---- S = Q K^T (bf16x3) ----
        float s[8][4];
#pragma unroll
        for (int nt = 0; nt < 8; ++nt)
#pragma unroll
            for (int e = 0; e < 4; ++e) s[nt][e] = 0.f;

#pragma unroll
        for (int ks = 0; ks < 4; ++ks) {
            uint32_t aoff = (uint32_t)(((m0w + (lane & 15)) * 72 + ks * 16 + ((lane >> 4) << 3)) * 2);
            uint32_t ah[4], al[4];
            ldsm_x4(ah, Qhi_b + aoff);
            ldsm_x4(al, Qlo_b + aoff);
#pragma unroll
            for (int nt = 0; nt < 8; ++nt) {
                uint32_t boff = (uint32_t)(((nt * 8 + (lane & 7)) * 72 + ks * 16 + (((lane >> 3) & 1) << 3)) * 2) + kOff;
                uint32_t bh[2], bl[2];
                ldsm_x2(bh, Khi_b + boff);
                ldsm_x2(bl, Klo_b + boff);
                mma16816(s[nt], ah, bh);
                mma16816(s[nt], ah, bl);
                mma16816(s[nt], al, bh);
            }
        }

        // ---- mask + online softmax ----
        float mx_g = -INFINITY, mx_g8 = -INFINITY;
#pragma unroll
        for (int nt = 0; nt < 8; ++nt) {
            float k0v = km[buf * 64 + nt * 8 + 2 * tg];
            float k1v = km[buf * 64 + nt * 8 + 2 * tg + 1];
            s[nt][0] = (qok_g  * k0v != 0.f) ? s[nt][0] : -1e9f;
            s[nt][1] = (qok_g  * k1v != 0.f) ? s[nt][1] : -1e9f;
            s[nt][2] = (qok_g8 * k0v != 0.f) ? s[nt][2] : -1e9f;
            s[nt][3] = (qok_g8 * k1v != 0.f) ? s[nt][3] : -1e9f;
            mx_g  = fmaxf(mx_g,  fmaxf(s[nt][0], s[nt][1]));
            mx_g8 = fmaxf(mx_g8, fmaxf(s[nt][2], s[nt][3]));
        }
#pragma unroll
        for (int off = 1; off <= 2; off <<= 1) {
            mx_g  = fmaxf(mx_g,  __shfl_xor_sync(0xffffffffu, mx_g,  off));
            mx_g8 = fmaxf(mx_g8, __shfl_xor_sync(0xffffffffu, mx_g8, off));
        }
        float mn_g  = fmaxf(m_g,  mx_g);
        float mn_g8 = fmaxf(m_g8, mx_g8);
        float alpha_g  = __expf(m_g  - mn_g);
        float alpha_g8 = __expf(m_g8 - mn_g8);
        m_g = mn_g; m_g8 = mn_g8;

        float sum_g = 0.f, sum_g8 = 0.f;
#pragma unroll
        for (int nt = 0; nt < 8; ++nt) {
            s[nt][0] = __expf(s[nt][0] - mn_g);
            s[nt][1] = __expf(s[nt][1] - mn_g);
            s[nt][2] = __expf(s[nt][2] - mn_g8);
            s[nt][3] = __expf(s[nt][3] - mn_g8);
            sum_g  += s[nt][0] + s[nt][1];
            sum_g8 += s[nt][2] + s[nt][3];
        }
#pragma unroll
        for (int off = 1; off <= 2; off <<= 1) {
            sum_g  += __shfl_xor_sync(0xffffffffu, sum_g,  off);
            sum_g8 += __shfl_xor_sync(0xffffffffu, sum_g8, off);
        }
        l_g  = l_g  * alpha_g  + sum_g;
        l_g8 = l_g8 * alpha_g8 + sum_g8;
#pragma unroll
        for (int nt = 0; nt < 8; ++nt) {
            o[nt][0] *= alpha_g;  o[nt][1] *= alpha_g;
            o[nt][2] *= alpha_g8; o[nt][3] *= alpha_g8;
        }

        // ---- O += P V (bf16x3, P from registers) ----
        const uint32_t vOff = kOff;
#pragma unroll
        for (int ks = 0; ks < 4; ++ks) {
            uint32_t ahi[4], alo[4];
            {
                float p0 = s[2 * ks][0], p1 = s[2 * ks][1];
                float p2 = s[2 * ks][2], p3 = s[2 * ks][3];
                float q0f = s[2 * ks + 1][0], q1f = s[2 * ks + 1][1];
                float q2f = s[2 * ks + 1][2], q3f = s[2 * ks + 1][3];
                ahi[0] = cvt2_bf16(p0, p1);
                ahi[1] = cvt2_bf16(p2, p3);
                ahi[2] = cvt2_bf16(q0f, q1f);
                ahi[3] = cvt2_bf16(q2f, q3f);
                __nv_bfloat162 t;
                t = *(__nv_bfloat162*)&ahi[0];
                alo[0] = cvt2_bf16(p0 - __bfloat162float(t.x), p1 - __bfloat162float(t.y));
                t = *(__nv_bfloat162*)&ahi[1];
                alo[1] = cvt2_bf16(p2 - __bfloat162float(t.x), p3 - __bfloat162float(t.y));
                t = *(__nv_bfloat162*)&ahi[2];
                alo[2] = cvt2_bf16(q0f - __bfloat162float(t.x), q1f - __bfloat162float(t.y));
                t = *(__nv_bfloat162*)&ahi[3];
                alo[3] = cvt2_bf16(q2f - __bfloat162float(t.x), q3f - __bfloat162float(t.y));
            }
#pragma unroll
            for (int nt = 0; nt < 8; ++nt) {
                uint32_t voff = (uint32_t)(((ks * 16 + (lane & 15)) * 72 + nt * 8) * 2) + vOff;
                uint32_t bh[2], bl[2];
                ldsm_x2_trans(bh, Vhi_b + voff);
                ldsm_x2_trans(bl, Vlo_b + voff);
                mma16816(o[nt], ahi, bh);
                mma16816(o[nt], alo, bh);
                mma16816(o[nt], ahi, bl);
            }
        }
    }

    // ---- epilogue ----
    float inv_g  = 1.f / l_g;
    float inv_g8 = 1.f / l_g8;
    const size_t row_g  = (size_t)(b * kTQ + q0 + m0w + g) * kC + h * 64;
    const size_t row_g8 = row_g + 8 * kC;
#pragma unroll
    for (int nt = 0; nt < 8; ++nt) {
        int col = nt * 8 + 2 * tg;
        *(float2*)(Out + row_g  + col) = make_float2(o[nt][0] * inv_g,  o[nt][1] * inv_g);
        *(float2*)(Out + row_g8 + col) = make_float2(o[nt][2] * inv_g8, o[nt][3] * inv_g8);
    }
}

// ---------------------------------------------------------------------------
extern "C" void kernel_launch(void* const* d_in, const int* in_sizes, int n_in,
                              void* d_out, int out_size) {
    const float* x_q  = (const float*)d_in[0];
    const float* x_kv = (const float*)d_in[1];
    const int* q_mask  = (const int*)d_in[2];
    const int* kv_mask = (const int*)d_in[3];
    const float* W_q  = (const float*)d_in[4];
    const float* W_kv = (const float*)d_in[5];
    const float* W_c  = (const float*)d_in[6];
    float* out = (float*)d_out;

    void* p;
    cudaGetSymbolAddress(&p, g_q);    float* gq  = (float*)p;
    cudaGetSymbolAddress(&p, g_kv);   float* gkv = (float*)p;
    cudaGetSymbolAddress(&p, g_attn); float* gat = (float*)p;

    rope_tables_kernel<<<(kTKV * 32 + 255) / 256, 256>>>();

    gemm_bf16x3_kernel<<<dim3(kC / 128, kM / 128), 256>>>(x_q, W_q, gq, kM, kC, kC);
    gemm_bf16x3_kernel<<<dim3(2 * kC / 128, kM / 128), 256>>>(x_kv, W_kv, gkv, kM, 2 * kC, kC);

    int rope_threads = kM * (kC / 2);
    rope_apply_kernel<<<(rope_threads + 255) / 256, 256>>>(gq, kC);
    rope_apply_kernel<<<(rope_threads + 255) / 256, 256>>>(gkv, 2 * kC);

    cudaFuncSetAttribute(flash_mma_kernel, cudaFuncAttributeMaxDynamicSharedMemorySize, kFlashSmem);
    flash_mma_kernel<<<dim3(kTQ / 128, kH, kB), 256, kFlashSmem>>>(gq, gkv, q_mask, kv_mask, gat);

    gemm_bf16x3_kernel<<<dim3(kC / 128, kM / 128), 256>>>(gat, W_c, out, kM, kC, kC);
}

// round 7
// speedup vs baseline: 2.8039x; 1.0813x over previous
#include <cuda_runtime.h>
#include <cuda_bf16.h>
#include <math.h>
#include <stdint.h>

constexpr int kB   = 4;
constexpr int kTQ  = 2048;
constexpr int kTKV = 2048;
constexpr int kC   = 1024;
constexpr int kD   = 64;
constexpr int kH   = 16;
constexpr int kM   = kB * kTQ;

// RoPE tables
__device__ float g_sin[kTKV * (kD / 2)];
__device__ float g_cos[kTKV * (kD / 2)];
// pre-split inputs [M,K] bf16
__device__ __nv_bfloat16 g_xqh[(size_t)kM * kC],  g_xql[(size_t)kM * kC];
__device__ __nv_bfloat16 g_xkvh[(size_t)kM * kC], g_xkvl[(size_t)kM * kC];
// transposed+split weights [N,K] bf16
__device__ __nv_bfloat16 g_wqTh[1024 * 1024],  g_wqTl[1024 * 1024];
__device__ __nv_bfloat16 g_wkvTh[2048 * 1024], g_wkvTl[2048 * 1024];
__device__ __nv_bfloat16 g_wcTh[1024 * 1024],  g_wcTl[1024 * 1024];
// projected, rope'd, split activations
__device__ __nv_bfloat16 g_qh[(size_t)kM * kC], g_ql[(size_t)kM * kC];
__device__ __nv_bfloat16 g_kh[(size_t)kM * kC], g_kl[(size_t)kM * kC];
__device__ __nv_bfloat16 g_vh[(size_t)kM * kC], g_vl[(size_t)kM * kC];
// attention output, split
__device__ __nv_bfloat16 g_ah[(size_t)kM * kC], g_al[(size_t)kM * kC];

// ---------------------------------------------------------------------------
__device__ __forceinline__ uint32_t smem_u32(const void* p) {
    return (uint32_t)__cvta_generic_to_shared(p);
}
__device__ __forceinline__ void ldsm_x4(uint32_t* r, uint32_t addr) {
    asm volatile("ldmatrix.sync.aligned.m8n8.x4.shared.b16 {%0,%1,%2,%3}, [%4];"
                 : "=r"(r[0]), "=r"(r[1]), "=r"(r[2]), "=r"(r[3]) : "r"(addr));
}
__device__ __forceinline__ void ldsm_x2(uint32_t* r, uint32_t addr) {
    asm volatile("ldmatrix.sync.aligned.m8n8.x2.shared.b16 {%0,%1}, [%2];"
                 : "=r"(r[0]), "=r"(r[1]) : "r"(addr));
}
__device__ __forceinline__ void ldsm_x2_trans(uint32_t* r, uint32_t addr) {
    asm volatile("ldmatrix.sync.aligned.m8n8.x2.trans.shared.b16 {%0,%1}, [%2];"
                 : "=r"(r[0]), "=r"(r[1]) : "r"(addr));
}
__device__ __forceinline__ void mma16816(float* c, const uint32_t* a, const uint32_t* b) {
    asm volatile(
        "mma.sync.aligned.m16n8k16.row.col.f32.bf16.bf16.f32 "
        "{%0,%1,%2,%3}, {%4,%5,%6,%7}, {%8,%9}, {%0,%1,%2,%3};\n"
        : "+f"(c[0]), "+f"(c[1]), "+f"(c[2]), "+f"(c[3])
        : "r"(a[0]), "r"(a[1]), "r"(a[2]), "r"(a[3]), "r"(b[0]), "r"(b[1]));
}
__device__ __forceinline__ void split_bf16(float x, __nv_bfloat16& h, __nv_bfloat16& l) {
    h = __float2bfloat16(x);
    l = __float2bfloat16(x - __bfloat162float(h));
}
__device__ __forceinline__ uint32_t pack2(__nv_bfloat16 a, __nv_bfloat16 b) {
    __nv_bfloat162 t; t.x = a; t.y = b;
    return *reinterpret_cast<uint32_t*>(&t);
}
__device__ __forceinline__ uint32_t cvt2_bf16(float lo, float hi) {
    uint32_t r;
    asm("cvt.rn.bf16x2.f32 %0, %1, %2;" : "=r"(r) : "f"(hi), "f"(lo));
    return r;
}

// ---------------------------------------------------------------------------
__global__ void rope_tables_kernel() {
    int idx = blockIdx.x * blockDim.x + threadIdx.x;
    if (idx >= kTKV * (kD / 2)) return;
    int t = idx >> 5;
    int i = idx & 31;
    double freq = pow(10000.0, -((2.0 * i + 1.0) / (double)kD));
    double ang = (double)(t + 1) * freq;
    g_sin[idx] = (float)sin(ang);
    g_cos[idx] = (float)cos(ang);
}

// split fp32 -> bf16 hi/lo, same layout
__global__ void split_x_kernel(const float* __restrict__ X,
                               __nv_bfloat16* __restrict__ H,
                               __nv_bfloat16* __restrict__ L, int total4) {
    int idx = blockIdx.x * blockDim.x + threadIdx.x;
    if (idx >= total4) return;
    float4 v = ((const float4*)X)[idx];
    __nv_bfloat16 h0, h1, h2, h3, l0, l1, l2, l3;
    split_bf16(v.x, h0, l0); split_bf16(v.y, h1, l1);
    split_bf16(v.z, h2, l2); split_bf16(v.w, h3, l3);
    ((uint2*)H)[idx] = make_uint2(pack2(h0, h1), pack2(h2, h3));
    ((uint2*)L)[idx] = make_uint2(pack2(l0, l1), pack2(l2, l3));
}

// W[K,N] fp32 -> WT hi/lo [N,K] bf16
__global__ void transpose_split_kernel(const float* __restrict__ W,
                                       __nv_bfloat16* __restrict__ Thi,
                                       __nv_bfloat16* __restrict__ Tlo,
                                       int K, int N) {
    __shared__ float t[32][33];
    int n0 = blockIdx.x * 32, k0 = blockIdx.y * 32;
    for (int r = threadIdx.y; r < 32; r += 8)
        t[r][threadIdx.x] = W[(size_t)(k0 + r) * N + n0 + threadIdx.x];
    __syncthreads();
    for (int r = threadIdx.y; r < 32; r += 8) {
        float v = t[threadIdx.x][r];
        __nv_bfloat16 h, l;
        split_bf16(v, h, l);
        size_t o = (size_t)(n0 + r) * K + k0 + threadIdx.x;
        Thi[o] = h;
        Tlo[o] = l;
    }
}

// ---------------------------------------------------------------------------
// Pre-split bf16x3 GEMM: C = A @ B, A [M,K] hi/lo bf16 row-major,
// B as [N,K] hi/lo bf16 (pre-transposed). CTA 128x128x32, 8 warps.
// MODE 0: fp32 C. MODE 1: rope+0.125 scale+split -> Qh/Ql.
// MODE 2: cols<1024 rope+split -> Kh/Kl; cols>=1024 split -> Vh/Vl.
// ---------------------------------------------------------------------------
constexpr int kLD = 40;

template <int MODE>
__global__ __launch_bounds__(256)
void gemm_ps_kernel(const __nv_bfloat16* __restrict__ Ah,
                    const __nv_bfloat16* __restrict__ Al,
                    const __nv_bfloat16* __restrict__ Bh,
                    const __nv_bfloat16* __restrict__ Bl,
                    float* __restrict__ Cf,
                    __nv_bfloat16* __restrict__ O1h, __nv_bfloat16* __restrict__ O1l,
                    __nv_bfloat16* __restrict__ O2h, __nv_bfloat16* __restrict__ O2l,
                    int M, int N, int K) {
    __shared__ __align__(16) __nv_bfloat16 sAh[128 * kLD];
    __shared__ __align__(16) __nv_bfloat16 sAl[128 * kLD];
    __shared__ __align__(16) __nv_bfloat16 sBh[128 * kLD];
    __shared__ __align__(16) __nv_bfloat16 sBl[128 * kLD];

    const int tid  = threadIdx.x;
    const int warp = tid >> 5, lane = tid & 31;
    const int wm = warp >> 2, wn = warp & 3;
    const int m0 = blockIdx.y * 128, n0 = blockIdx.x * 128;

    const int row = tid >> 1;
    const int ko  = (tid & 1) * 16;
    const __nv_bfloat16* aH = Ah + (size_t)(m0 + row) * K + ko;
    const __nv_bfloat16* aL = Al + (size_t)(m0 + row) * K + ko;
    const __nv_bfloat16* bH = Bh + (size_t)(n0 + row) * K + ko;
    const __nv_bfloat16* bL = Bl + (size_t)(n0 + row) * K + ko;

    uint4 pAh[2], pAl[2], pBh[2], pBl[2];
#pragma unroll
    for (int u = 0; u < 2; ++u) {
        pAh[u] = *(const uint4*)(aH + u * 8);
        pAl[u] = *(const uint4*)(aL + u * 8);
        pBh[u] = *(const uint4*)(bH + u * 8);
        pBl[u] = *(const uint4*)(bL + u * 8);
    }

    float acc[4][4][4];
#pragma unroll
    for (int mt = 0; mt < 4; ++mt)
#pragma unroll
        for (int nt = 0; nt < 4; ++nt)
#pragma unroll
            for (int e = 0; e < 4; ++e) acc[mt][nt][e] = 0.f;

    const uint32_t sAh_b = smem_u32(sAh), sAl_b = smem_u32(sAl);
    const uint32_t sBh_b = smem_u32(sBh), sBl_b = smem_u32(sBl);
    const int g8 = lane & 7, tq = lane >> 3;

    const int nk = K / 32;
    for (int kt = 0; kt < nk; ++kt) {
#pragma unroll
        for (int u = 0; u < 2; ++u) {
            *(uint4*)&sAh[row * kLD + ko + u * 8] = pAh[u];
            *(uint4*)&sAl[row * kLD + ko + u * 8] = pAl[u];
            *(uint4*)&sBh[row * kLD + ko + u * 8] = pBh[u];
            *(uint4*)&sBl[row * kLD + ko + u * 8] = pBl[u];
        }
        __syncthreads();

        if (kt + 1 < nk) {
            int kc = (kt + 1) * 32;
#pragma unroll
            for (int u = 0; u < 2; ++u) {
                pAh[u] = *(const uint4*)(aH + kc + u * 8);
                pAl[u] = *(const uint4*)(aL + kc + u * 8);
                pBh[u] = *(const uint4*)(bH + kc + u * 8);
                pBl[u] = *(const uint4*)(bL + kc + u * 8);
            }
        }

#pragma unroll
        for (int s = 0; s < 2; ++s) {
            uint32_t bh[4][2], bl[4][2];
#pragma unroll
            for (int nt = 0; nt < 4; ++nt) {
                uint32_t off = (uint32_t)(((wn * 32 + nt * 8 + g8) * kLD + s * 16 + ((tq & 1) << 3)) * 2);
                ldsm_x2(bh[nt], sBh_b + off);
                ldsm_x2(bl[nt], sBl_b + off);
            }
#pragma unroll
            for (int mt = 0; mt < 4; ++mt) {
                uint32_t offA = (uint32_t)(((wm * 64 + mt * 16 + ((tq & 1) << 3) + g8) * kLD
                                            + s * 16 + ((tq >> 1) << 3)) * 2);
                uint32_t ah[4], al[4];
                ldsm_x4(ah, sAh_b + offA);
                ldsm_x4(al, sAl_b + offA);
#pragma unroll
                for (int nt = 0; nt < 4; ++nt) {
                    mma16816(acc[mt][nt], ah, bh[nt]);
                    mma16816(acc[mt][nt], ah, bl[nt]);
                    mma16816(acc[mt][nt], al, bh[nt]);
                }
            }
        }
        __syncthreads();
    }

    // epilogue
    const int gq = lane >> 2, tg2 = 2 * (lane & 3);
#pragma unroll
    for (int mt = 0; mt < 4; ++mt) {
#pragma unroll
        for (int nt = 0; nt < 4; ++nt) {
            int col = n0 + wn * 32 + nt * 8 + tg2;
#pragma unroll
            for (int half = 0; half < 2; ++half) {
                int r = m0 + wm * 64 + mt * 16 + gq + half * 8;
                float x = acc[mt][nt][half * 2 + 0];
                float y = acc[mt][nt][half * 2 + 1];
                if (MODE == 0) {
                    *(float2*)(Cf + (size_t)r * N + col) = make_float2(x, y);
                } else if (MODE == 1) {
                    int t = r & (kTQ - 1);
                    int i = (col & 63) >> 1;
                    float si = g_sin[t * 32 + i], co = g_cos[t * 32 + i];
                    float xq = (x * co - y * si) * 0.125f;
                    float yq = (x * si + y * co) * 0.125f;
                    __nv_bfloat16 h0, h1, l0, l1;
                    split_bf16(xq, h0, l0);
                    split_bf16(yq, h1, l1);
                    size_t o = (size_t)r * kC + col;
                    *(uint32_t*)(O1h + o) = pack2(h0, h1);
                    *(uint32_t*)(O1l + o) = pack2(l0, l1);
                } else {  // MODE 2
                    if (col < kC) {
                        int t = r & (kTKV - 1);
                        int i = (col & 63) >> 1;
                        float si = g_sin[t * 32 + i], co = g_cos[t * 32 + i];
                        float xk = x * co - y * si;
                        float yk = x * si + y * co;
                        __nv_bfloat16 h0, h1, l0, l1;
                        split_bf16(xk, h0, l0);
                        split_bf16(yk, h1, l1);
                        size_t o = (size_t)r * kC + col;
                        *(uint32_t*)(O1h + o) = pack2(h0, h1);
                        *(uint32_t*)(O1l + o) = pack2(l0, l1);
                    } else {
                        __nv_bfloat16 h0, h1, l0, l1;
                        split_bf16(x, h0, l0);
                        split_bf16(y, h1, l1);
                        size_t o = (size_t)r * kC + (col - kC);
                        *(uint32_t*)(O2h + o) = pack2(h0, h1);
                        *(uint32_t*)(O2l + o) = pack2(l0, l1);
                    }
                }
            }
        }
    }
}

// ---------------------------------------------------------------------------
// Flash attention on pre-split bf16 Q/K/V. Writes split bf16 output.
// CTA = (128 q-rows, h, b); 8 warps x 16 rows; KV tiles of 64, double-buffered.
// ---------------------------------------------------------------------------
constexpr int kFQ = 128 * 72;
constexpr int kFT = 64 * 72;
constexpr int kFlashSmem = (2 * kFQ + 8 * kFT) * 2 + 2 * 64 * 4;

__global__ __launch_bounds__(256, 2)
void flash_mma_kernel(const __nv_bfloat16* __restrict__ Qh, const __nv_bfloat16* __restrict__ Ql,
                      const __nv_bfloat16* __restrict__ Kh, const __nv_bfloat16* __restrict__ Kl,
                      const __nv_bfloat16* __restrict__ Vh, const __nv_bfloat16* __restrict__ Vl,
                      const int* __restrict__ qmask, const int* __restrict__ kvmask,
                      __nv_bfloat16* __restrict__ Oh, __nv_bfloat16* __restrict__ Ol) {
    extern __shared__ char smc[];
    __nv_bfloat16* Qhi = (__nv_bfloat16*)smc;
    __nv_bfloat16* Qlo = Qhi + kFQ;
    __nv_bfloat16* Khi = Qlo + kFQ;
    __nv_bfloat16* Klo = Khi + 2 * kFT;
    __nv_bfloat16* Vhi = Klo + 2 * kFT;
    __nv_bfloat16* Vlo = Vhi + 2 * kFT;
    float* km = (float*)(Vlo + 2 * kFT);

    const int tid = threadIdx.x;
    const int warp = tid >> 5, lane = tid & 31;
    const int g = lane >> 2, tg = lane & 3;
    const int m0w = warp * 16;
    const int q0 = blockIdx.x * 128;
    const int h  = blockIdx.y;
    const int b  = blockIdx.z;

    {
        int row = tid >> 1, cb = (tid & 1) * 32;
        size_t src = (size_t)(b * kTQ + q0 + row) * kC + h * 64 + cb;
        int dst = row * 72 + cb;
#pragma unroll
        for (int u = 0; u < 4; ++u) {
            *(uint4*)&Qhi[dst + u * 8] = *(const uint4*)(Qh + src + u * 8);
            *(uint4*)&Qlo[dst + u * 8] = *(const uint4*)(Ql + src + u * 8);
        }
    }
    {
        int j = tid >> 2, cb = (tid & 3) * 16;
        size_t src = (size_t)(b * kTKV + j) * kC + h * 64 + cb;
        int dst = j * 72 + cb;
#pragma unroll
        for (int u = 0; u < 2; ++u) {
            *(uint4*)&Khi[dst + u * 8] = *(const uint4*)(Kh + src + u * 8);
            *(uint4*)&Klo[dst + u * 8] = *(const uint4*)(Kl + src + u * 8);
            *(uint4*)&Vhi[dst + u * 8] = *(const uint4*)(Vh + src + u * 8);
            *(uint4*)&Vlo[dst + u * 8] = *(const uint4*)(Vl + src + u * 8);
        }
        if (tid < 64) km[tid] = (kvmask[b * kTKV + tid] != 0) ? 1.f : 0.f;
    }

    const float qok_g  = (qmask[b * kTQ + q0 + m0w + g]     != 0) ? 1.f : 0.f;
    const float qok_g8 = (qmask[b * kTQ + q0 + m0w + g + 8] != 0) ? 1.f : 0.f;

    float o[8][4];
#pragma unroll
    for (int nt = 0; nt < 8; ++nt)
#pragma unroll
        for (int e = 0; e < 4; ++e) o[nt][e] = 0.f;
    float m_g = -INFINITY, m_g8 = -INFINITY, l_g = 0.f, l_g8 = 0.f;

    const uint32_t Qhi_b = smem_u32(Qhi), Qlo_b = smem_u32(Qlo);
    const uint32_t Khi_b = smem_u32(Khi), Klo_b = smem_u32(Klo);
    const uint32_t Vhi_b = smem_u32(Vhi), Vlo_b = smem_u32(Vlo);

    const int nTiles = kTKV / 64;
    for (int kt = 0; kt < nTiles; ++kt) {
        __syncthreads();
        const int buf = kt & 1;
        const uint32_t kOff = (uint32_t)buf * (kFT * 2);

        if (kt + 1 < nTiles) {
            int k0n = (kt + 1) * 64;
            int nb = buf ^ 1;
            int j = tid >> 2, cb = (tid & 3) * 16;
            size_t src = (size_t)(b * kTKV + k0n + j) * kC + h * 64 + cb;
            int dst = nb * kFT + j * 72 + cb;
#pragma unroll
            for (int u = 0; u < 2; ++u) {
                *(uint4*)&Khi[dst + u * 8] = *(const uint4*)(Kh + src + u * 8);
                *(uint4*)&Klo[dst + u * 8] = *(const uint4*)(Kl + src + u * 8);
                *(uint4*)&Vhi[dst + u * 8] = *(const uint4*)(Vh + src + u * 8);
                *(uint4*)&Vlo[dst + u * 8] = *(const uint4*)(Vl + src + u * 8);
            }
            if (tid < 64) km[nb * 64 + tid] = (kvmask[b * kTKV + k0n + tid] != 0) ? 1.f : 0.f;
        }

        float s[8][4];
#pragma unroll
        for (int nt = 0; nt < 8; ++nt)
#pragma unroll
            for (int e = 0; e < 4; ++e) s[nt][e] = 0.f;

#pragma unroll
        for (int ks = 0; ks < 4; ++ks) {
            uint32_t aoff = (uint32_t)(((m0w + (lane & 15)) * 72 + ks * 16 + ((lane >> 4) << 3)) * 2);
            uint32_t ah[4], al[4];
            ldsm_x4(ah, Qhi_b + aoff);
            ldsm_x4(al, Qlo_b + aoff);
#pragma unroll
            for (int nt = 0; nt < 8; ++nt) {
                uint32_t boff = (uint32_t)(((nt * 8 + (lane & 7)) * 72 + ks * 16 + (((lane >> 3) & 1) << 3)) * 2) + kOff;
                uint32_t bh[2], bl[2];
                ldsm_x2(bh, Khi_b + boff);
                ldsm_x2(bl, Klo_b + boff);
                mma16816(s[nt], ah, bh);
                mma16816(s[nt], ah, bl);
                mma16816(s[nt], al, bh);
            }
        }

        float mx_g = -INFINITY, mx_g8 = -INFINITY;
#pragma unroll
        for (int nt = 0; nt < 8; ++nt) {
            float k0v = km[buf * 64 + nt * 8 + 2 * tg];
            float k1v = km[buf * 64 + nt * 8 + 2 * tg + 1];
            s[nt][0] = (qok_g  * k0v != 0.f) ? s[nt][0] : -1e9f;
            s[nt][1] = (qok_g  * k1v != 0.f) ? s[nt][1] : -1e9f;
            s[nt][2] = (qok_g8 * k0v != 0.f) ? s[nt][2] : -1e9f;
            s[nt][3] = (qok_g8 * k1v != 0.f) ? s[nt][3] : -1e9f;
            mx_g  = fmaxf(mx_g,  fmaxf(s[nt][0], s[nt][1]));
            mx_g8 = fmaxf(mx_g8, fmaxf(s[nt][2], s[nt][3]));
        }
#pragma unroll
        for (int off = 1; off <= 2; off <<= 1) {
            mx_g  = fmaxf(mx_g,  __shfl_xor_sync(0xffffffffu, mx_g,  off));
            mx_g8 = fmaxf(mx_g8, __shfl_xor_sync(0xffffffffu, mx_g8, off));
        }
        float mn_g  = fmaxf(m_g,  mx_g);
        float mn_g8 = fmaxf(m_g8, mx_g8);
        float alpha_g  = __expf(m_g  - mn_g);
        float alpha_g8 = __expf(m_g8 - mn_g8);
        m_g = mn_g; m_g8 = mn_g8;

        float sum_g = 0.f, sum_g8 = 0.f;
#pragma unroll
        for (int nt = 0; nt < 8; ++nt) {
            s[nt][0] = __expf(s[nt][0] - mn_g);
            s[nt][1] = __expf(s[nt][1] - mn_g);
            s[nt][2] = __expf(s[nt][2] - mn_g8);
            s[nt][3] = __expf(s[nt][3] - mn_g8);
            sum_g  += s[nt][0] + s[nt][1];
            sum_g8 += s[nt][2] + s[nt][3];
        }
#pragma unroll
        for (int off = 1; off <= 2; off <<= 1) {
            sum_g  += __shfl_xor_sync(0xffffffffu, sum_g,  off);
            sum_g8 += __shfl_xor_sync(0xffffffffu, sum_g8, off);
        }
        l_g  = l_g  * alpha_g  + sum_g;
        l_g8 = l_g8 * alpha_g8 + sum_g8;
#pragma unroll
        for (int nt = 0; nt < 8; ++nt) {
            o[nt][0] *= alpha_g;  o[nt][1] *= alpha_g;
            o[nt][2] *= alpha_g8; o[nt][3] *= alpha_g8;
        }

        const uint32_t vOff = kOff;
#pragma unroll
        for (int ks = 0; ks < 4; ++ks) {
            uint32_t ahi[4], alo[4];
            {
                float p0 = s[2 * ks][0], p1 = s[2 * ks][1];
                float p2 = s[2 * ks][2], p3 = s[2 * ks][3];
                float q0f = s[2 * ks + 1][0], q1f = s[2 * ks + 1][1];
                float q2f = s[2 * ks + 1][2], q3f = s[2 * ks + 1][3];
                ahi[0] = cvt2_bf16(p0, p1);
                ahi[1] = cvt2_bf16(p2, p3);
                ahi[2] = cvt2_bf16(q0f, q1f);
                ahi[3] = cvt2_bf16(q2f, q3f);
                __nv_bfloat162 t;
                t = *(__nv_bfloat162*)&ahi[0];
                alo[0] = cvt2_bf16(p0 - __bfloat162float(t.x), p1 - __bfloat162float(t.y));
                t = *(__nv_bfloat162*)&ahi[1];
                alo[1] = cvt2_bf16(p2 - __bfloat162float(t.x), p3 - __bfloat162float(t.y));
                t = *(__nv_bfloat162*)&ahi[2];
                alo[2] = cvt2_bf16(q0f - __bfloat162float(t.x), q1f - __bfloat162float(t.y));
                t = *(__nv_bfloat162*)&ahi[3];
                alo[3] = cvt2_bf16(q2f - __bfloat162float(t.x), q3f - __bfloat162float(t.y));
            }
#pragma unroll
            for (int nt = 0; nt < 8; ++nt) {
                uint32_t voff = (uint32_t)(((ks * 16 + (lane & 15)) * 72 + nt * 8) * 2) + vOff;
                uint32_t bh[2], bl[2];
                ldsm_x2_trans(bh, Vhi_b + voff);
                ldsm_x2_trans(bl, Vlo_b + voff);
                mma16816(o[nt], ahi, bh);
                mma16816(o[nt], alo, bh);
                mma16816(o[nt], ahi, bl);
            }
        }
    }

    float inv_g  = 1.f / l_g;
    float inv_g8 = 1.f / l_g8;
    const size_t row_g  = (size_t)(b * kTQ + q0 + m0w + g) * kC + h * 64;
    const size_t row_g8 = row_g + 8 * kC;
#pragma unroll
    for (int nt = 0; nt < 8; ++nt) {
        int col = nt * 8 + 2 * tg;
        {
            float x = o[nt][0] * inv_g, y = o[nt][1] * inv_g;
            __nv_bfloat16 h0, h1, l0, l1;
            split_bf16(x, h0, l0);
            split_bf16(y, h1, l1);
            *(uint32_t*)(Oh + row_g + col) = pack2(h0, h1);
            *(uint32_t*)(Ol + row_g + col) = pack2(l0, l1);
        }
        {
            float x = o[nt][2] * inv_g8, y = o[nt][3] * inv_g8;
            __nv_bfloat16 h0, h1, l0, l1;
            split_bf16(x, h0, l0);
            split_bf16(y, h1, l1);
            *(uint32_t*)(Oh + row_g8 + col) = pack2(h0, h1);
            *(uint32_t*)(Ol + row_g8 + col) = pack2(l0, l1);
        }
    }
}

// ---------------------------------------------------------------------------
extern "C" void kernel_launch(void* const* d_in, const int* in_sizes, int n_in,
                              void* d_out, int out_size) {
    const float* x_q  = (const float*)d_in[0];
    const float* x_kv = (const float*)d_in[1];
    const int* q_mask  = (const int*)d_in[2];
    const int* kv_mask = (const int*)d_in[3];
    const float* W_q  = (const float*)d_in[4];
    const float* W_kv = (const float*)d_in[5];
    const float* W_c  = (const float*)d_in[6];
    float* out = (float*)d_out;

    void* p;
    __nv_bfloat16 *xqh, *xql, *xkvh, *xkvl;
    __nv_bfloat16 *wqh, *wql, *wkvh, *wkvl, *wch, *wcl;
    __nv_bfloat16 *qh, *ql, *kh, *kl, *vh, *vl, *ah, *al;
    cudaGetSymbolAddress(&p, g_xqh);  xqh  = (__nv_bfloat16*)p;
    cudaGetSymbolAddress(&p, g_xql);  xql  = (__nv_bfloat16*)p;
    cudaGetSymbolAddress(&p, g_xkvh); xkvh = (__nv_bfloat16*)p;
    cudaGetSymbolAddress(&p, g_xkvl); xkvl = (__nv_bfloat16*)p;
    cudaGetSymbolAddress(&p, g_wqTh);  wqh  = (__nv_bfloat16*)p;
    cudaGetSymbolAddress(&p, g_wqTl);  wql  = (__nv_bfloat16*)p;
    cudaGetSymbolAddress(&p, g_wkvTh); wkvh = (__nv_bfloat16*)p;
    cudaGetSymbolAddress(&p, g_wkvTl); wkvl = (__nv_bfloat16*)p;
    cudaGetSymbolAddress(&p, g_wcTh);  wch  = (__nv_bfloat16*)p;
    cudaGetSymbolAddress(&p, g_wcTl);  wcl  = (__nv_bfloat16*)p;
    cudaGetSymbolAddress(&p, g_qh); qh = (__nv_bfloat16*)p;
    cudaGetSymbolAddress(&p, g_ql); ql = (__nv_bfloat16*)p;
    cudaGetSymbolAddress(&p, g_kh); kh = (__nv_bfloat16*)p;
    cudaGetSymbolAddress(&p, g_kl); kl = (__nv_bfloat16*)p;
    cudaGetSymbolAddress(&p, g_vh); vh = (__nv_bfloat16*)p;
    cudaGetSymbolAddress(&p, g_vl); vl = (__nv_bfloat16*)p;
    cudaGetSymbolAddress(&p, g_ah); ah = (__nv_bfloat16*)p;
    cudaGetSymbolAddress(&p, g_al); al = (__nv_bfloat16*)p;

    rope_tables_kernel<<<(kTKV * 32 + 255) / 256, 256>>>();

    int total4 = kM * kC / 4;
    split_x_kernel<<<(total4 + 255) / 256, 256>>>(x_q,  xqh,  xql,  total4);
    split_x_kernel<<<(total4 + 255) / 256, 256>>>(x_kv, xkvh, xkvl, total4);
    transpose_split_kernel<<<dim3(1024 / 32, 1024 / 32), dim3(32, 8)>>>(W_q,  wqh,  wql,  1024, 1024);
    transpose_split_kernel<<<dim3(2048 / 32, 1024 / 32), dim3(32, 8)>>>(W_kv, wkvh, wkvl, 1024, 2048);
    transpose_split_kernel<<<dim3(1024 / 32, 1024 / 32), dim3(32, 8)>>>(W_c,  wch,  wcl,  1024, 1024);

    // Q projection + rope + scale + split
    gemm_ps_kernel<1><<<dim3(kC / 128, kM / 128), 256>>>(
        xqh, xql, wqh, wql, nullptr, qh, ql, nullptr, nullptr, kM, kC, kC);
    // KV projection + rope(K) + split
    gemm_ps_kernel<2><<<dim3(2 * kC / 128, kM / 128), 256>>>(
        xkvh, xkvl, wkvh, wkvl, nullptr, kh, kl, vh, vl, kM, 2 * kC, kC);

    cudaFuncSetAttribute(flash_mma_kernel, cudaFuncAttributeMaxDynamicSharedMemorySize, kFlashSmem);
    flash_mma_kernel<<<dim3(kTQ / 128, kH, kB), 256, kFlashSmem>>>(
        qh, ql, kh, kl, vh, vl, q_mask, kv_mask, ah, al);

    // output projection -> fp32 out
    gemm_ps_kernel<0><<<dim3(kC / 128, kM / 128), 256>>>(
        ah, al, wch, wcl, out, nullptr, nullptr, nullptr, nullptr, kM, kC, kC);
}